// round 13
// baseline (speedup 1.0000x reference)
#include <cuda_runtime.h>
#include <cuda_bf16.h>
#include <cuda_fp16.h>
#include <cooperative_groups.h>
#include <cstdint>
#include <cstddef>

namespace cg = cooperative_groups;

#define HID   256
#define T_SEQ 1024
#define NB    64
#define CL    16                       // CTAs per cluster

// ---------------- scratch (device globals; no allocation) ----------------
__device__ __half g_h1h[(size_t)NB * T_SEQ * 512];    // layer-0 out, fp16
__device__ __half g_w1h[(size_t)2 * 1024 * 512];      // W_ih_l1 fp16
__device__ float g_gx[(size_t)2 * T_SEQ * NB * 1024]; // layer-1 projected gates
__device__ float g_feat[NB * 512];
__device__ float g_y[NB * 256];

__device__ __forceinline__ float sigf(float x) {
    return __fdividef(1.0f, 1.0f + __expf(-x));
}
__device__ __forceinline__ float tanh_fast(float x) {
    float e = __expf(2.0f * x);
    return 1.0f - __fdividef(2.0f, e + 1.0f);
}

// mma.sync m16n8k16 row.col fp16 -> f32 (validated fragment layout)
__device__ __forceinline__ void mma_f16(float* c, const uint32_t* a,
                                        uint32_t b0, uint32_t b1) {
    asm volatile(
        "mma.sync.aligned.m16n8k16.row.col.f32.f16.f16.f32 "
        "{%0,%1,%2,%3}, {%4,%5,%6,%7}, {%8,%9}, {%0,%1,%2,%3};"
        : "+f"(c[0]), "+f"(c[1]), "+f"(c[2]), "+f"(c[3])
        : "r"(a[0]), "r"(a[1]), "r"(a[2]), "r"(a[3]), "r"(b0), "r"(b1));
}

__device__ __forceinline__ void ldsm4(uint32_t* r, uint32_t addr) {
    asm volatile(
        "ldmatrix.sync.aligned.m8n8.x4.shared.b16 {%0,%1,%2,%3}, [%4];"
        : "=r"(r[0]), "=r"(r[1]), "=r"(r[2]), "=r"(r[3]) : "r"(addr));
}

__device__ __forceinline__ uint32_t smem_u32(const void* p) {
    uint32_t a;
    asm("{ .reg .u64 t; cvta.to.shared.u64 t, %1; cvt.u32.u64 %0, t; }" : "=r"(a) : "l"(p));
    return a;
}

__device__ __forceinline__ uint32_t pack_f16(float a, float b) {
    __half2 v = __floats2half2_rn(a, b);
    return *reinterpret_cast<uint32_t*>(&v);
}
__device__ __forceinline__ float f16_res(float x) {
    return x - __half2float(__float2half_rn(x));
}

#define MBAR_INIT(a, c) \
    asm volatile("mbarrier.init.shared.b64 [%0], %1;" :: "r"(a), "r"((uint32_t)(c)) : "memory")

#define MBAR_WAIT_CL(a, par) do {                                                   \
    uint32_t _m = (a), _p = (par);                                                  \
    asm volatile("{\n\t.reg .pred P1;\n\t"                                          \
        "WLC_%=:\n\t"                                                               \
        "mbarrier.try_wait.parity.acquire.cluster.shared::cta.b64 P1, [%0], %1;\n\t"\
        "@P1 bra.uni WDC_%=;\n\t"                                                   \
        "bra.uni WLC_%=;\n\t"                                                       \
        "WDC_%=:\n\t}" :: "r"(_m), "r"(_p) : "memory");                             \
} while (0)

#define MBAR_ARRIVE_REMOTE(a) \
    asm volatile("mbarrier.arrive.release.cluster.shared::cluster.b64 _, [%0];" \
                 :: "r"(a) : "memory")

#define CLUSTER_ARRIVE() asm volatile("barrier.cluster.arrive.aligned;" ::: "memory")
#define CLUSTER_WAIT()   asm volatile("barrier.cluster.wait.aligned;" ::: "memory")
#define NBAR_SYNC(id)    asm volatile("bar.sync %0, 128;" :: "r"(id) : "memory")

// =====================================================================
// Recurrent LSTM: 16-CTA clusters (128 SMs), both dirs per CTA via
// separate 4-warp groups + per-dir named barriers (validated R12).
// Each CTA owns 16 units per dir; warp wg = gate wg over those 16 units:
// 2 n8 tiles x 16 ks = 32 HMMA/warp/step -> 64 HMMA/SMSP per step-pair.
// A tile M=16 (rows 0-7 h_hi fp16, 8-15 h_lo residual), full 256-k in
// SMEM, double-buffered per dir. Push-based mbarrier exchange: each warp
// pushes its 32 owned items (2 batches x 8 pairs x hi/lo), one per lane,
// to all 16 peers; arrive count 64 = 16 CTAs x 4 warps.
// =====================================================================
template<int LAYER>
__global__ void __launch_bounds__(256, 1) __cluster_dims__(CL, 1, 1)
lstm_rec(const float* __restrict__ x, const int* __restrict__ lengths,
         const float* __restrict__ Wih, const float* __restrict__ Whh,
         const float* __restrict__ bih, const float* __restrict__ bhh)
{
    __shared__ __align__(16) uint32_t Ahl[4 * 2112];   // [dir][buf][16*132]
    __shared__ __align__(16) float gates_s[2][8 * 68]; // [dir][batch][gate*16+u]
    __shared__ __align__(8)  uint64_t mbars[4];        // [dir][buf]

    const int tid   = threadIdx.x;
    const int lane  = tid & 31;
    const int g     = lane >> 2;
    const int t4    = lane & 3;
    uint32_t crank;
    asm("mov.u32 %0, %%cluster_ctarank;" : "=r"(crank));
    const int bg    = blockIdx.x >> 4;     // batch group (8 clusters)
    const int d     = tid >> 7;            // direction of this warp group
    const int wg    = (tid >> 5) & 3;      // warp-in-group == gate index
    const int W     = wg;                  // alias

    // update-thread identity: 128 threads/group, each owns (batch, unit)
    const int gt     = tid & 127;
    const int b_upd  = gt >> 4;            // 0..7
    const int u      = gt & 15;            // unit 0..15 (local)
    const int uglob  = (int)crank * 16 + u;
    const int bglob  = bg * 8 + b_upd;
    const int L      = lengths[bglob];

    // ---- W_hh fragments (fp16): warp wg covers gate wg, units crank*16 + j*8+g
    uint32_t wf[16][2][2];
    #pragma unroll
    for (int j = 0; j < 2; j++) {
        int grow = d * 1024 + wg * 256 + (int)crank * 16 + j * 8 + g;
        const float* wp = Whh + (size_t)grow * 256;
        #pragma unroll
        for (int ks = 0; ks < 16; ks++) {
            #pragma unroll
            for (int s = 0; s < 2; s++) {
                int kp = ks * 8 + t4 + s * 4;
                float2 wv = *reinterpret_cast<const float2*>(wp + kp * 2);
                wf[ks][j][s] = pack_f16(wv.x, wv.y);
            }
        }
    }

    // ---- layer-0 input projection params (IN = 3) for 1 unit
    float wi[4][3], bs[4];
    if (LAYER == 0) {
        #pragma unroll
        for (int q = 0; q < 4; q++) {
            int r0 = d * 1024 + q * 256 + uglob;
            wi[q][0] = Wih[(size_t)r0 * 3 + 0];
            wi[q][1] = Wih[(size_t)r0 * 3 + 1];
            wi[q][2] = Wih[(size_t)r0 * 3 + 2];
            bs[q]    = bih[r0] + bhh[r0];
        }
    }

    for (int i = tid; i < 4 * 2112; i += 256) Ahl[i] = 0u;
    const uint32_t mbase = smem_u32(mbars);
    if (tid == 0) {
        #pragma unroll
        for (int i = 0; i < 4; i++) MBAR_INIT(mbase + i * 8, 64);
        asm volatile("fence.mbarrier_init.release.cluster;" ::: "memory");
    }
    __syncthreads();
    CLUSTER_ARRIVE();
    CLUSTER_WAIT();

    // ---- peer addresses (16 peers)
    const uint32_t tbase = smem_u32(Ahl);
    uint32_t peerT[CL], peerM[CL];
    #pragma unroll
    for (int pe = 0; pe < CL; pe++) {
        asm("mapa.shared::cluster.u32 %0, %1, %2;" : "=r"(peerT[pe]) : "r"(tbase), "r"(pe));
        asm("mapa.shared::cluster.u32 %0, %1, %2;" : "=r"(peerM[pe]) : "r"(mbase), "r"(pe));
    }

    const int lrow  = lane & 15;
    const int lcoff = (lane >> 4) * 4;
    const uint32_t aB0 = tbase + (uint32_t)((d * 2 + 0) * 2112 + lrow * 132 + lcoff) * 4u;
    const uint32_t aB1 = tbase + (uint32_t)((d * 2 + 1) * 2112 + lrow * 132 + lcoff) * 4u;

    // push mapping: lane = half*16 + b_loc*8 + pr; sources in same warp
    const int p_pr   = lane & 7;            // unit pair 0..7
    const int p_bl   = (lane >> 3) & 1;     // batch-in-warp
    const int p_half = lane >> 4;           // 0 = hi rows, 1 = lo rows
    const int p_s0   = p_bl * 16 + 2 * p_pr;      // lane holding unit 2pr
    const int p_s1   = p_s0 + 1;                  // lane holding unit 2pr+1
    const uint32_t p_row = (uint32_t)((2 * W + p_bl) + p_half * 8);
    const uint32_t p_col = (uint32_t)((int)crank * 8 + p_pr);

    const float* gx_base = g_gx + ((size_t)d * T_SEQ * NB + bglob) * 1024 + uglob;

    float c = 0.0f, h = 0.0f;
    int ph0 = 0, ph1 = 0;

    float p0, p1, p2, p3;
    if (LAYER == 1) {
        const float* gp = gx_base;
        p0 = __ldg(gp);       p1 = __ldg(gp + 256);
        p2 = __ldg(gp + 512); p3 = __ldg(gp + 768);
    }

    for (int t = 0; t < T_SEQ; t++) {
        const bool m = (t < L);

        if (LAYER == 0) {
            int teff = (d == 0) ? t : (m ? (L - 1 - t) : t);
            const float* xp = x + ((size_t)bglob * T_SEQ + teff) * 3;
            float x0 = xp[0], x1 = xp[1], x2 = xp[2];
            p0 = bs[0] + wi[0][0]*x0 + wi[0][1]*x1 + wi[0][2]*x2;
            p1 = bs[1] + wi[1][0]*x0 + wi[1][1]*x1 + wi[1][2]*x2;
            p2 = bs[2] + wi[2][0]*x0 + wi[2][1]*x1 + wi[2][2]*x2;
            p3 = bs[3] + wi[3][0]*x0 + wi[3][1]*x1 + wi[3][2]*x2;
        }

        // ---- wait for this step's A tile of OWN dir (t=0 reads zeros)
        const int buf = t & 1;
        if (t > 0) {
            if (buf) { MBAR_WAIT_CL(mbase + (uint32_t)(d * 2 + 1) * 8u, ph1); ph1 ^= 1; }
            else     { MBAR_WAIT_CL(mbase + (uint32_t)(d * 2 + 0) * 8u, ph0); ph0 ^= 1; }
        }
        const uint32_t aBase = buf ? aB1 : aB0;

        // ---- matvec: 2 independent chains (2 n8 tiles), 32 HMMA/warp
        float acc0[4] = {0.f, 0.f, 0.f, 0.f};
        float acc1[4] = {0.f, 0.f, 0.f, 0.f};
        #pragma unroll
        for (int ks = 0; ks < 16; ks++) {
            uint32_t a[4];
            ldsm4(a, aBase + (uint32_t)ks * 32u);
            mma_f16(acc0, a, wf[ks][0][0], wf[ks][0][1]);
            mma_f16(acc1, a, wf[ks][1][0], wf[ks][1][1]);
        }

        // ---- dump gates: row g = batch; hi rows (c0,c1) + lo rows (c2,c3)
        *reinterpret_cast<float2*>(&gates_s[d][g * 68 + wg * 16 + 2 * t4]) =
            make_float2(acc0[0] + acc0[2], acc0[1] + acc0[3]);
        *reinterpret_cast<float2*>(&gates_s[d][g * 68 + wg * 16 + 8 + 2 * t4]) =
            make_float2(acc1[0] + acc1[2], acc1[1] + acc1[3]);
        NBAR_SYNC(d + 1);

        // ---- update 1 unit: gates at [batch][gate*16 + u]
        float q0 = p0 + gates_s[d][b_upd * 68 +       u];
        float q1 = p1 + gates_s[d][b_upd * 68 +  16 + u];
        float q2 = p2 + gates_s[d][b_upd * 68 +  32 + u];
        float q3 = p3 + gates_s[d][b_upd * 68 +  48 + u];
        float ig = sigf(q0), fg = sigf(q1);
        float gg = tanh_fast(q2), og = sigf(q3);
        float cn = fmaf(fg, c, ig * gg);
        float hn = og * tanh_fast(cn);
        if (m) { c = cn; h = hn; }

        // ---- push owned items into all 16 peers' tile[d][nb], then arrive
        if (t + 1 < T_SEQ) {
            const uint32_t nb = (uint32_t)((t + 1) & 1);
            float v0 = __shfl_sync(0xffffffffu, h, p_s0);
            float v1 = __shfl_sync(0xffffffffu, h, p_s1);
            uint32_t val = p_half ? pack_f16(f16_res(v0), f16_res(v1))
                                  : pack_f16(v0, v1);
            const uint32_t off =
                (((uint32_t)(d * 2) + nb) * 2112u + p_row * 132u + p_col) * 4u;
            #pragma unroll
            for (int pe = 0; pe < CL; pe++)
                asm volatile("st.shared::cluster.b32 [%0], %1;"
                             :: "r"(peerT[pe] + off), "r"(val) : "memory");
            __syncwarp();
            if (lane < CL)
                MBAR_ARRIVE_REMOTE(peerM[lane] + ((uint32_t)(d * 2) + nb) * 8u);
        }

        // ---- next-step g_gx prefetch (long cover)
        if (LAYER == 1) {
            int tn = (t + 1 < T_SEQ) ? t + 1 : t;
            const float* gp = gx_base + (size_t)tn * NB * 1024;
            p0 = __ldg(gp);       p1 = __ldg(gp + 256);
            p2 = __ldg(gp + 512); p3 = __ldg(gp + 768);
        }

        // ---- global stores (off critical path)
        if (LAYER == 0) {
            int pos = (d == 0) ? t : (m ? (L - 1 - t) : t);
            float val = m ? h : 0.0f;
            g_h1h[((size_t)bglob * T_SEQ + pos) * 512 + d * 256 + uglob] =
                __float2half_rn(val);
        } else if (d == 1 && t == 0) {
            g_feat[bglob * 512 + 256 + uglob] = h;
        }
    }

    if (LAYER == 1 && d == 0)
        g_feat[bglob * 512 + uglob] = h;

    CLUSTER_ARRIVE();
    CLUSTER_WAIT();
}

// =====================================================================
// W_ih_l1 fp32 -> fp16
// =====================================================================
__global__ void __launch_bounds__(256) conv_w1(const float* __restrict__ Wih)
{
    size_t i = (size_t)blockIdx.x * 1024 + threadIdx.x * 4;
    float4 v = *reinterpret_cast<const float4*>(Wih + i);
    g_w1h[i + 0] = __float2half_rn(v.x);
    g_w1h[i + 1] = __float2half_rn(v.y);
    g_w1h[i + 2] = __float2half_rn(v.z);
    g_w1h[i + 3] = __float2half_rn(v.w);
}

// =====================================================================
// Layer-1 input projection via fp16 HMMA (unchanged, validated).
// =====================================================================
__global__ void __launch_bounds__(256) gx_mma(
    const int* __restrict__ lengths,
    const float* __restrict__ bih, const float* __restrict__ bhh)
{
    __shared__ __align__(16) uint32_t Ax[64 * 20];
    __shared__ __align__(16) uint32_t Bx[128 * 20];
    __shared__ float bias_s[128];

    const int tid  = threadIdx.x;
    const int wid  = tid >> 5;
    const int lane = tid & 31;
    const int g    = lane >> 2;
    const int t4   = lane & 3;
    const int n0   = blockIdx.x * 128;
    const int t    = blockIdx.y;
    const int dir  = blockIdx.z;

    const int m0 = (wid & 1) * 32;
    const int nw = (wid >> 1) * 32;

    const int ar = tid >> 2, ac = tid & 3;
    const int br = tid >> 1, bc = tid & 1;
    if (tid < 128) bias_s[tid] = bih[dir * 1024 + n0 + tid] + bhh[dir * 1024 + n0 + tid];

    const int La = lengths[ar];
    const int teff = dir ? ((t < La) ? (La - 1 - t) : t) : t;
    const uint4* a_p = (const uint4*)(g_h1h + ((size_t)ar * T_SEQ + teff) * 512) + ac;
    const uint4* b_p = (const uint4*)(g_w1h + ((size_t)(dir * 1024 + n0 + br)) * 512) + bc * 2;

    float acc[2][4][4];
    #pragma unroll
    for (int i = 0; i < 2; i++)
        #pragma unroll
        for (int j = 0; j < 4; j++)
            #pragma unroll
            for (int k = 0; k < 4; k++) acc[i][j][k] = 0.0f;

    uint4 va  = __ldg(a_p);
    uint4 vb0 = __ldg(b_p), vb1 = __ldg(b_p + 1);

    for (int kc = 0; kc < 16; kc++) {
        *reinterpret_cast<uint4*>(&Ax[ar * 20 + ac * 4]) = va;
        *reinterpret_cast<uint4*>(&Bx[br * 20 + bc * 8])     = vb0;
        *reinterpret_cast<uint4*>(&Bx[br * 20 + bc * 8 + 4]) = vb1;
        __syncthreads();

        if (kc + 1 < 16) {
            va  = __ldg(a_p + (kc + 1) * 4);
            vb0 = __ldg(b_p + (kc + 1) * 4);
            vb1 = __ldg(b_p + (kc + 1) * 4 + 1);
        }

        #pragma unroll
        for (int ks = 0; ks < 2; ks++) {
            uint32_t a[2][4];
            #pragma unroll
            for (int mf = 0; mf < 2; mf++) {
                int r = m0 + mf * 16 + g;
                a[mf][0] = Ax[r * 20 + ks * 8 + t4];
                a[mf][1] = Ax[(r + 8) * 20 + ks * 8 + t4];
                a[mf][2] = Ax[r * 20 + ks * 8 + t4 + 4];
                a[mf][3] = Ax[(r + 8) * 20 + ks * 8 + t4 + 4];
            }
            #pragma unroll
            for (int nf = 0; nf < 4; nf++) {
                int rn = nw + nf * 8 + g;
                uint32_t b0 = Bx[rn * 20 + ks * 8 + t4];
                uint32_t b1 = Bx[rn * 20 + ks * 8 + t4 + 4];
                mma_f16(acc[0][nf], a[0], b0, b1);
                mma_f16(acc[1][nf], a[1], b0, b1);
            }
        }
        __syncthreads();
    }

    float* gxp = g_gx + ((size_t)(dir * T_SEQ + t) * NB) * 1024 + n0;
    #pragma unroll
    for (int mf = 0; mf < 2; mf++) {
        int bi = m0 + mf * 16 + g;
        #pragma unroll
        for (int nf = 0; nf < 4; nf++) {
            int nn = nw + nf * 8 + t4 * 2;
            float bv0 = bias_s[nn], bv1 = bias_s[nn + 1];
            float2 v0 = make_float2(acc[mf][nf][0] + bv0, acc[mf][nf][1] + bv1);
            float2 v1 = make_float2(acc[mf][nf][2] + bv0, acc[mf][nf][3] + bv1);
            *reinterpret_cast<float2*>(gxp + (size_t)bi * 1024 + nn)       = v0;
            *reinterpret_cast<float2*>(gxp + (size_t)(bi + 8) * 1024 + nn) = v1;
        }
    }
}

// =====================================================================
// Head
// =====================================================================
__global__ void __launch_bounds__(256) head_fc1(const float* __restrict__ fc1_w,
                                                const float* __restrict__ fc1_b)
{
    __shared__ __align__(16) float fs[512];
    int b = blockIdx.x, n = threadIdx.x;
    for (int i = n; i < 512; i += 256) fs[i] = g_feat[b * 512 + i];
    __syncthreads();
    const float4* wp = reinterpret_cast<const float4*>(fc1_w + (size_t)n * 512);
    const float4* fp = reinterpret_cast<const float4*>(fs);
    float acc = fc1_b[n];
    #pragma unroll 4
    for (int k = 0; k < 128; k++) {
        float4 w4 = __ldg(wp + k);
        float4 f4 = fp[k];
        acc += w4.x * f4.x + w4.y * f4.y + w4.z * f4.z + w4.w * f4.w;
    }
    g_y[b * 256 + n] = fmaxf(acc, 0.0f);
}

__global__ void head_bn(const float* __restrict__ gamma, const float* __restrict__ beta)
{
    int n = threadIdx.x;
    float s = 0.0f, s2 = 0.0f;
    for (int b = 0; b < 64; b++) {
        float v = g_y[b * 256 + n];
        s += v; s2 += v * v;
    }
    float mean = s * 0.015625f;
    float var  = s2 * 0.015625f - mean * mean;
    float inv  = rsqrtf(var + 1e-5f);
    float ga = gamma[n] * inv, be = beta[n];
    for (int b = 0; b < 64; b++)
        g_y[b * 256 + n] = (g_y[b * 256 + n] - mean) * ga + be;
}

__global__ void __launch_bounds__(256) head_out(const float* __restrict__ W,
                                                const float* __restrict__ bias,
                                                float* __restrict__ out)
{
    __shared__ __align__(16) float ys[256];
    int b = blockIdx.x;
    ys[threadIdx.x] = g_y[b * 256 + threadIdx.x];
    __syncthreads();
    int o = threadIdx.x;
    if (o < 196) {
        const float4* wp = reinterpret_cast<const float4*>(W + (size_t)o * 256);
        const float4* yp = reinterpret_cast<const float4*>(ys);
        float acc = bias[o];
        #pragma unroll 4
        for (int k = 0; k < 64; k++) {
            float4 w4 = __ldg(wp + k);
            float4 y4 = yp[k];
            acc += w4.x * y4.x + w4.y * y4.y + w4.z * y4.z + w4.w * y4.w;
        }
        out[(size_t)b * 196 + o] = acc;
    }
}

// =====================================================================
extern "C" void kernel_launch(void* const* d_in, const int* in_sizes, int n_in,
                              void* d_out, int out_size)
{
    const float* x       = (const float*)d_in[0];
    const int*   lengths = (const int*)  d_in[1];
    const float* Wih0    = (const float*)d_in[2];
    const float* Whh0    = (const float*)d_in[3];
    const float* bih0    = (const float*)d_in[4];
    const float* bhh0    = (const float*)d_in[5];
    const float* Wih1    = (const float*)d_in[6];
    const float* Whh1    = (const float*)d_in[7];
    const float* bih1    = (const float*)d_in[8];
    const float* bhh1    = (const float*)d_in[9];
    const float* fc1_w   = (const float*)d_in[10];
    const float* fc1_b   = (const float*)d_in[11];
    const float* gamma   = (const float*)d_in[12];
    const float* beta    = (const float*)d_in[13];
    const float* fcow    = (const float*)d_in[14];
    const float* fcob    = (const float*)d_in[15];
    float* out = (float*)d_out;

    // allow 16-CTA clusters (non-portable size); host-side config, no alloc
    cudaFuncSetAttribute(lstm_rec<0>,
                         cudaFuncAttributeNonPortableClusterSizeAllowed, 1);
    cudaFuncSetAttribute(lstm_rec<1>,
                         cudaFuncAttributeNonPortableClusterSizeAllowed, 1);

    conv_w1<<<1024, 256>>>(Wih1);
    lstm_rec<0><<<128, 256>>>(x, lengths, Wih0, Whh0, bih0, bhh0);
    gx_mma<<<dim3(8, 1024, 2), 256>>>(lengths, bih1, bhh1);
    lstm_rec<1><<<128, 256>>>(x, lengths, Wih1, Whh1, bih1, bhh1);
    head_fc1<<<64, 256>>>(fc1_w, fc1_b);
    head_bn<<<1, 256>>>(gamma, beta);
    head_out<<<64, 256>>>(fcow, fcob, out);
}

// round 14
// speedup vs baseline: 1.7876x; 1.7876x over previous
#include <cuda_runtime.h>
#include <cuda_bf16.h>
#include <cuda_fp16.h>
#include <cooperative_groups.h>
#include <cstdint>
#include <cstddef>

namespace cg = cooperative_groups;

#define HID   256
#define T_SEQ 1024
#define NB    64

// ---------------- scratch (device globals; no allocation) ----------------
__device__ __half g_h1h[(size_t)NB * T_SEQ * 512];    // layer-0 out, fp16
__device__ __half g_w1h[(size_t)2 * 1024 * 512];      // W_ih_l1 fp16
__device__ float g_gx[(size_t)2 * T_SEQ * NB * 1024]; // layer-1 projected gates
__device__ float g_feat[NB * 512];
__device__ float g_y[NB * 256];

__device__ __forceinline__ float sigf(float x) {
    return __fdividef(1.0f, 1.0f + __expf(-x));
}
__device__ __forceinline__ float tanh_fast(float x) {
    float e = __expf(2.0f * x);
    return 1.0f - __fdividef(2.0f, e + 1.0f);
}

// mma.sync m16n8k16 row.col fp16 -> f32 (validated fragment layout)
__device__ __forceinline__ void mma_f16(float* c, const uint32_t* a,
                                        uint32_t b0, uint32_t b1) {
    asm volatile(
        "mma.sync.aligned.m16n8k16.row.col.f32.f16.f16.f32 "
        "{%0,%1,%2,%3}, {%4,%5,%6,%7}, {%8,%9}, {%0,%1,%2,%3};"
        : "+f"(c[0]), "+f"(c[1]), "+f"(c[2]), "+f"(c[3])
        : "r"(a[0]), "r"(a[1]), "r"(a[2]), "r"(a[3]), "r"(b0), "r"(b1));
}

__device__ __forceinline__ void ldsm4(uint32_t* r, uint32_t addr) {
    asm volatile(
        "ldmatrix.sync.aligned.m8n8.x4.shared.b16 {%0,%1,%2,%3}, [%4];"
        : "=r"(r[0]), "=r"(r[1]), "=r"(r[2]), "=r"(r[3]) : "r"(addr));
}

__device__ __forceinline__ uint32_t smem_u32(const void* p) {
    uint32_t a;
    asm("{ .reg .u64 t; cvta.to.shared.u64 t, %1; cvt.u32.u64 %0, t; }" : "=r"(a) : "l"(p));
    return a;
}

__device__ __forceinline__ uint32_t pack_f16(float a, float b) {
    __half2 v = __floats2half2_rn(a, b);
    return *reinterpret_cast<uint32_t*>(&v);
}
__device__ __forceinline__ float f16_res(float x) {
    return x - __half2float(__float2half_rn(x));
}

#define MBAR_INIT(a, c) \
    asm volatile("mbarrier.init.shared.b64 [%0], %1;" :: "r"(a), "r"((uint32_t)(c)) : "memory")

#define MBAR_WAIT_CL(a, par) do {                                                   \
    uint32_t _m = (a), _p = (par);                                                  \
    asm volatile("{\n\t.reg .pred P1;\n\t"                                          \
        "WLC_%=:\n\t"                                                               \
        "mbarrier.try_wait.parity.acquire.cluster.shared::cta.b64 P1, [%0], %1;\n\t"\
        "@P1 bra.uni WDC_%=;\n\t"                                                   \
        "bra.uni WLC_%=;\n\t"                                                       \
        "WDC_%=:\n\t}" :: "r"(_m), "r"(_p) : "memory");                             \
} while (0)

#define MBAR_ARRIVE_REMOTE(a) \
    asm volatile("mbarrier.arrive.release.cluster.shared::cluster.b64 _, [%0];" \
                 :: "r"(a) : "memory")

#define CLUSTER_ARRIVE() asm volatile("barrier.cluster.arrive.aligned;" ::: "memory")
#define CLUSTER_WAIT()   asm volatile("barrier.cluster.wait.aligned;" ::: "memory")
#define NBAR_SYNC(id)    asm volatile("bar.sync %0, 128;" :: "r"(id) : "memory")

// =====================================================================
// Recurrent LSTM: 64 CTAs (8-CTA clusters, validated sweet spot), 512
// threads = 4 warp-groups (dir x unit-half), each 4 warps (warp = gate
// over 16 units: 16 ldsm + 32 HMMA/step). 4 independent latency chains
// per SMSP hide each other's wait/update/push under HMMA issue.
// A tile M=16 per dir (rows 0-7 h_hi fp16, 8-15 h_lo residual), double
// buffered; mbars live at the tail of the tile array (single mapa set).
// Push exchange: each warp pushes its 2 batches x 8 pairs x hi/lo to all
// 8 peers; arrive count 64 = 8 CTAs x 8 warps per dir.
// =====================================================================
template<int LAYER>
__global__ void __launch_bounds__(512, 1) __cluster_dims__(8, 1, 1)
lstm_rec(const float* __restrict__ x, const int* __restrict__ lengths,
         const float* __restrict__ Wih, const float* __restrict__ Whh,
         const float* __restrict__ bih, const float* __restrict__ bhh)
{
    // [dir][buf][16*132] tiles, then 4 mbars (u64) at tail offset 8448 u32
    __shared__ __align__(16) uint32_t Ahl[4 * 2112 + 16];
    __shared__ __align__(16) float gates_s[2][2][8 * 68];

    const int tid   = threadIdx.x;
    const int lane  = tid & 31;
    const int g     = lane >> 2;
    const int t4    = lane & 3;
    uint32_t crank;
    asm("mov.u32 %0, %%cluster_ctarank;" : "=r"(crank));
    const int bg  = blockIdx.x >> 3;       // batch group
    const int G   = tid >> 7;              // warp-group 0..3
    const int d   = G >> 1;                // direction
    const int uh  = G & 1;                 // unit-half
    const int wg  = (tid >> 5) & 3;        // warp-in-group == gate
    // warp-in-dir index 0..7 (for arrive accounting only)

    // update-thread identity: 128 threads/group own (batch, unit)
    const int gt     = tid & 127;
    const int b_upd  = gt >> 4;            // 0..7
    const int ug     = gt & 15;            // unit within group
    const int uglob  = (int)crank * 32 + uh * 16 + ug;
    const int bglob  = bg * 8 + b_upd;
    const int L      = lengths[bglob];

    // ---- W_hh fragments (fp16): warp = gate wg over group's 16 units
    uint32_t wf[16][2][2];
    #pragma unroll
    for (int j = 0; j < 2; j++) {
        int grow = d * 1024 + wg * 256 + (int)crank * 32 + uh * 16 + j * 8 + g;
        const float* wp = Whh + (size_t)grow * 256;
        #pragma unroll
        for (int ks = 0; ks < 16; ks++) {
            #pragma unroll
            for (int s = 0; s < 2; s++) {
                int kp = ks * 8 + t4 + s * 4;
                float2 wv = *reinterpret_cast<const float2*>(wp + kp * 2);
                wf[ks][j][s] = pack_f16(wv.x, wv.y);
            }
        }
    }

    // ---- layer-0 input projection params (IN = 3) for 1 unit
    float wi[4][3], bs[4];
    if (LAYER == 0) {
        #pragma unroll
        for (int q = 0; q < 4; q++) {
            int r0 = d * 1024 + q * 256 + uglob;
            wi[q][0] = Wih[(size_t)r0 * 3 + 0];
            wi[q][1] = Wih[(size_t)r0 * 3 + 1];
            wi[q][2] = Wih[(size_t)r0 * 3 + 2];
            bs[q]    = bih[r0] + bhh[r0];
        }
    }

    for (int i = tid; i < 4 * 2112 + 16; i += 512) Ahl[i] = 0u;
    const uint32_t tbase = smem_u32(Ahl);
    const uint32_t mboff = 4u * 2112u * 4u;          // byte offset of mbars
    if (tid == 0) {
        #pragma unroll
        for (int i = 0; i < 4; i++) MBAR_INIT(tbase + mboff + i * 8, 64);
        asm volatile("fence.mbarrier_init.release.cluster;" ::: "memory");
    }
    __syncthreads();
    CLUSTER_ARRIVE();
    CLUSTER_WAIT();

    // ---- peer base addresses (tiles; mbars derived by +mboff)
    uint32_t peerT[8];
    #pragma unroll
    for (int pe = 0; pe < 8; pe++)
        asm("mapa.shared::cluster.u32 %0, %1, %2;" : "=r"(peerT[pe]) : "r"(tbase), "r"(pe));

    const int lrow  = lane & 15;
    const int lcoff = (lane >> 4) * 4;
    const uint32_t aB0 = tbase + (uint32_t)((d * 2 + 0) * 2112 + lrow * 132 + lcoff) * 4u;
    const uint32_t aB1 = tbase + (uint32_t)((d * 2 + 1) * 2112 + lrow * 132 + lcoff) * 4u;

    // push mapping: lane = half*16 + bl*8 + pr
    const int p_pr   = lane & 7;                 // unit pair in group
    const int p_bl   = (lane >> 3) & 1;          // batch-in-warp
    const int p_half = lane >> 4;                // hi / lo rows
    const int p_s0   = p_bl * 16 + 2 * p_pr;     // lane with h(unit 2pr)
    const int p_s1   = p_s0 + 1;
    const uint32_t p_row = (uint32_t)((2 * wg + p_bl) + p_half * 8);
    const uint32_t p_col = (uint32_t)((int)crank * 16 + uh * 8 + p_pr);

    const float* gx_base = g_gx + ((size_t)d * T_SEQ * NB + bglob) * 1024 + uglob;

    float c = 0.0f, h = 0.0f;
    int ph0 = 0, ph1 = 0;

    float p0, p1, p2, p3;
    if (LAYER == 1) {
        const float* gp = gx_base;
        p0 = __ldg(gp);       p1 = __ldg(gp + 256);
        p2 = __ldg(gp + 512); p3 = __ldg(gp + 768);
    }

    for (int t = 0; t < T_SEQ; t++) {
        const bool m = (t < L);

        if (LAYER == 0) {
            int teff = (d == 0) ? t : (m ? (L - 1 - t) : t);
            const float* xp = x + ((size_t)bglob * T_SEQ + teff) * 3;
            float x0 = xp[0], x1 = xp[1], x2 = xp[2];
            p0 = bs[0] + wi[0][0]*x0 + wi[0][1]*x1 + wi[0][2]*x2;
            p1 = bs[1] + wi[1][0]*x0 + wi[1][1]*x1 + wi[1][2]*x2;
            p2 = bs[2] + wi[2][0]*x0 + wi[2][1]*x1 + wi[2][2]*x2;
            p3 = bs[3] + wi[3][0]*x0 + wi[3][1]*x1 + wi[3][2]*x2;
        }

        // ---- wait for this step's A tile of OWN dir (t=0 reads zeros)
        const int buf = t & 1;
        if (t > 0) {
            if (buf) { MBAR_WAIT_CL(tbase + mboff + (uint32_t)(d * 2 + 1) * 8u, ph1); ph1 ^= 1; }
            else     { MBAR_WAIT_CL(tbase + mboff + (uint32_t)(d * 2 + 0) * 8u, ph0); ph0 ^= 1; }
        }
        const uint32_t aBase = buf ? aB1 : aB0;

        // ---- matvec: 2 independent chains (2 n8 tiles), 32 HMMA/warp
        float acc0[4] = {0.f, 0.f, 0.f, 0.f};
        float acc1[4] = {0.f, 0.f, 0.f, 0.f};
        #pragma unroll
        for (int ks = 0; ks < 16; ks++) {
            uint32_t a[4];
            ldsm4(a, aBase + (uint32_t)ks * 32u);
            mma_f16(acc0, a, wf[ks][0][0], wf[ks][0][1]);
            mma_f16(acc1, a, wf[ks][1][0], wf[ks][1][1]);
        }

        // ---- dump gates: [batch][gate*16 + unit_in_group]
        float* gs = gates_s[d][uh];
        *reinterpret_cast<float2*>(&gs[g * 68 + wg * 16 + 2 * t4]) =
            make_float2(acc0[0] + acc0[2], acc0[1] + acc0[3]);
        *reinterpret_cast<float2*>(&gs[g * 68 + wg * 16 + 8 + 2 * t4]) =
            make_float2(acc1[0] + acc1[2], acc1[1] + acc1[3]);
        NBAR_SYNC(G + 1);

        // ---- update 1 unit
        float q0 = p0 + gs[b_upd * 68 +       ug];
        float q1 = p1 + gs[b_upd * 68 +  16 + ug];
        float q2 = p2 + gs[b_upd * 68 +  32 + ug];
        float q3 = p3 + gs[b_upd * 68 +  48 + ug];
        float ig = sigf(q0), fg = sigf(q1);
        float gg = tanh_fast(q2), og = sigf(q3);
        float cn = fmaf(fg, c, ig * gg);
        float hn = og * tanh_fast(cn);
        if (m) { c = cn; h = hn; }

        // ---- push owned items into all 8 peers' tile[d][nb], then arrive
        if (t + 1 < T_SEQ) {
            const uint32_t nb = (uint32_t)((t + 1) & 1);
            float v0 = __shfl_sync(0xffffffffu, h, p_s0);
            float v1 = __shfl_sync(0xffffffffu, h, p_s1);
            uint32_t val = p_half ? pack_f16(f16_res(v0), f16_res(v1))
                                  : pack_f16(v0, v1);
            const uint32_t off =
                (((uint32_t)(d * 2) + nb) * 2112u + p_row * 132u + p_col) * 4u;
            #pragma unroll
            for (int pe = 0; pe < 8; pe++)
                asm volatile("st.shared::cluster.b32 [%0], %1;"
                             :: "r"(peerT[pe] + off), "r"(val) : "memory");
            __syncwarp();
            if (lane < 8)
                MBAR_ARRIVE_REMOTE(peerT[lane] + mboff + ((uint32_t)(d * 2) + nb) * 8u);
        }

        // ---- next-step g_gx prefetch (long cover)
        if (LAYER == 1) {
            int tn = (t + 1 < T_SEQ) ? t + 1 : t;
            const float* gp = gx_base + (size_t)tn * NB * 1024;
            p0 = __ldg(gp);       p1 = __ldg(gp + 256);
            p2 = __ldg(gp + 512); p3 = __ldg(gp + 768);
        }

        // ---- global stores (off critical path)
        if (LAYER == 0) {
            int pos = (d == 0) ? t : (m ? (L - 1 - t) : t);
            float val = m ? h : 0.0f;
            g_h1h[((size_t)bglob * T_SEQ + pos) * 512 + d * 256 + uglob] =
                __float2half_rn(val);
        } else if (d == 1 && t == 0) {
            g_feat[bglob * 512 + 256 + uglob] = h;
        }
    }

    if (LAYER == 1 && d == 0)
        g_feat[bglob * 512 + uglob] = h;

    CLUSTER_ARRIVE();
    CLUSTER_WAIT();
}

// =====================================================================
// W_ih_l1 fp32 -> fp16
// =====================================================================
__global__ void __launch_bounds__(256) conv_w1(const float* __restrict__ Wih)
{
    size_t i = (size_t)blockIdx.x * 1024 + threadIdx.x * 4;
    float4 v = *reinterpret_cast<const float4*>(Wih + i);
    g_w1h[i + 0] = __float2half_rn(v.x);
    g_w1h[i + 1] = __float2half_rn(v.y);
    g_w1h[i + 2] = __float2half_rn(v.z);
    g_w1h[i + 3] = __float2half_rn(v.w);
}

// =====================================================================
// Layer-1 input projection via fp16 HMMA (unchanged, validated).
// =====================================================================
__global__ void __launch_bounds__(256) gx_mma(
    const int* __restrict__ lengths,
    const float* __restrict__ bih, const float* __restrict__ bhh)
{
    __shared__ __align__(16) uint32_t Ax[64 * 20];
    __shared__ __align__(16) uint32_t Bx[128 * 20];
    __shared__ float bias_s[128];

    const int tid  = threadIdx.x;
    const int wid  = tid >> 5;
    const int lane = tid & 31;
    const int g    = lane >> 2;
    const int t4   = lane & 3;
    const int n0   = blockIdx.x * 128;
    const int t    = blockIdx.y;
    const int dir  = blockIdx.z;

    const int m0 = (wid & 1) * 32;
    const int nw = (wid >> 1) * 32;

    const int ar = tid >> 2, ac = tid & 3;
    const int br = tid >> 1, bc = tid & 1;
    if (tid < 128) bias_s[tid] = bih[dir * 1024 + n0 + tid] + bhh[dir * 1024 + n0 + tid];

    const int La = lengths[ar];
    const int teff = dir ? ((t < La) ? (La - 1 - t) : t) : t;
    const uint4* a_p = (const uint4*)(g_h1h + ((size_t)ar * T_SEQ + teff) * 512) + ac;
    const uint4* b_p = (const uint4*)(g_w1h + ((size_t)(dir * 1024 + n0 + br)) * 512) + bc * 2;

    float acc[2][4][4];
    #pragma unroll
    for (int i = 0; i < 2; i++)
        #pragma unroll
        for (int j = 0; j < 4; j++)
            #pragma unroll
            for (int k = 0; k < 4; k++) acc[i][j][k] = 0.0f;

    uint4 va  = __ldg(a_p);
    uint4 vb0 = __ldg(b_p), vb1 = __ldg(b_p + 1);

    for (int kc = 0; kc < 16; kc++) {
        *reinterpret_cast<uint4*>(&Ax[ar * 20 + ac * 4]) = va;
        *reinterpret_cast<uint4*>(&Bx[br * 20 + bc * 8])     = vb0;
        *reinterpret_cast<uint4*>(&Bx[br * 20 + bc * 8 + 4]) = vb1;
        __syncthreads();

        if (kc + 1 < 16) {
            va  = __ldg(a_p + (kc + 1) * 4);
            vb0 = __ldg(b_p + (kc + 1) * 4);
            vb1 = __ldg(b_p + (kc + 1) * 4 + 1);
        }

        #pragma unroll
        for (int ks = 0; ks < 2; ks++) {
            uint32_t a[2][4];
            #pragma unroll
            for (int mf = 0; mf < 2; mf++) {
                int r = m0 + mf * 16 + g;
                a[mf][0] = Ax[r * 20 + ks * 8 + t4];
                a[mf][1] = Ax[(r + 8) * 20 + ks * 8 + t4];
                a[mf][2] = Ax[r * 20 + ks * 8 + t4 + 4];
                a[mf][3] = Ax[(r + 8) * 20 + ks * 8 + t4 + 4];
            }
            #pragma unroll
            for (int nf = 0; nf < 4; nf++) {
                int rn = nw + nf * 8 + g;
                uint32_t b0 = Bx[rn * 20 + ks * 8 + t4];
                uint32_t b1 = Bx[rn * 20 + ks * 8 + t4 + 4];
                mma_f16(acc[0][nf], a[0], b0, b1);
                mma_f16(acc[1][nf], a[1], b0, b1);
            }
        }
        __syncthreads();
    }

    float* gxp = g_gx + ((size_t)(dir * T_SEQ + t) * NB) * 1024 + n0;
    #pragma unroll
    for (int mf = 0; mf < 2; mf++) {
        int bi = m0 + mf * 16 + g;
        #pragma unroll
        for (int nf = 0; nf < 4; nf++) {
            int nn = nw + nf * 8 + t4 * 2;
            float bv0 = bias_s[nn], bv1 = bias_s[nn + 1];
            float2 v0 = make_float2(acc[mf][nf][0] + bv0, acc[mf][nf][1] + bv1);
            float2 v1 = make_float2(acc[mf][nf][2] + bv0, acc[mf][nf][3] + bv1);
            *reinterpret_cast<float2*>(gxp + (size_t)bi * 1024 + nn)       = v0;
            *reinterpret_cast<float2*>(gxp + (size_t)(bi + 8) * 1024 + nn) = v1;
        }
    }
}

// =====================================================================
// Head
// =====================================================================
__global__ void __launch_bounds__(256) head_fc1(const float* __restrict__ fc1_w,
                                                const float* __restrict__ fc1_b)
{
    __shared__ __align__(16) float fs[512];
    int b = blockIdx.x, n = threadIdx.x;
    for (int i = n; i < 512; i += 256) fs[i] = g_feat[b * 512 + i];
    __syncthreads();
    const float4* wp = reinterpret_cast<const float4*>(fc1_w + (size_t)n * 512);
    const float4* fp = reinterpret_cast<const float4*>(fs);
    float acc = fc1_b[n];
    #pragma unroll 4
    for (int k = 0; k < 128; k++) {
        float4 w4 = __ldg(wp + k);
        float4 f4 = fp[k];
        acc += w4.x * f4.x + w4.y * f4.y + w4.z * f4.z + w4.w * f4.w;
    }
    g_y[b * 256 + n] = fmaxf(acc, 0.0f);
}

__global__ void head_bn(const float* __restrict__ gamma, const float* __restrict__ beta)
{
    int n = threadIdx.x;
    float s = 0.0f, s2 = 0.0f;
    for (int b = 0; b < 64; b++) {
        float v = g_y[b * 256 + n];
        s += v; s2 += v * v;
    }
    float mean = s * 0.015625f;
    float var  = s2 * 0.015625f - mean * mean;
    float inv  = rsqrtf(var + 1e-5f);
    float ga = gamma[n] * inv, be = beta[n];
    for (int b = 0; b < 64; b++)
        g_y[b * 256 + n] = (g_y[b * 256 + n] - mean) * ga + be;
}

__global__ void __launch_bounds__(256) head_out(const float* __restrict__ W,
                                                const float* __restrict__ bias,
                                                float* __restrict__ out)
{
    __shared__ __align__(16) float ys[256];
    int b = blockIdx.x;
    ys[threadIdx.x] = g_y[b * 256 + threadIdx.x];
    __syncthreads();
    int o = threadIdx.x;
    if (o < 196) {
        const float4* wp = reinterpret_cast<const float4*>(W + (size_t)o * 256);
        const float4* yp = reinterpret_cast<const float4*>(ys);
        float acc = bias[o];
        #pragma unroll 4
        for (int k = 0; k < 64; k++) {
            float4 w4 = __ldg(wp + k);
            float4 y4 = yp[k];
            acc += w4.x * y4.x + w4.y * y4.y + w4.z * y4.z + w4.w * y4.w;
        }
        out[(size_t)b * 196 + o] = acc;
    }
}

// =====================================================================
extern "C" void kernel_launch(void* const* d_in, const int* in_sizes, int n_in,
                              void* d_out, int out_size)
{
    const float* x       = (const float*)d_in[0];
    const int*   lengths = (const int*)  d_in[1];
    const float* Wih0    = (const float*)d_in[2];
    const float* Whh0    = (const float*)d_in[3];
    const float* bih0    = (const float*)d_in[4];
    const float* bhh0    = (const float*)d_in[5];
    const float* Wih1    = (const float*)d_in[6];
    const float* Whh1    = (const float*)d_in[7];
    const float* bih1    = (const float*)d_in[8];
    const float* bhh1    = (const float*)d_in[9];
    const float* fc1_w   = (const float*)d_in[10];
    const float* fc1_b   = (const float*)d_in[11];
    const float* gamma   = (const float*)d_in[12];
    const float* beta    = (const float*)d_in[13];
    const float* fcow    = (const float*)d_in[14];
    const float* fcob    = (const float*)d_in[15];
    float* out = (float*)d_out;

    conv_w1<<<1024, 256>>>(Wih1);
    lstm_rec<0><<<64, 512>>>(x, lengths, Wih0, Whh0, bih0, bhh0);
    gx_mma<<<dim3(8, 1024, 2), 256>>>(lengths, bih1, bhh1);
    lstm_rec<1><<<64, 512>>>(x, lengths, Wih1, Whh1, bih1, bhh1);
    head_fc1<<<64, 256>>>(fc1_w, fc1_b);
    head_bn<<<1, 256>>>(gamma, beta);
    head_out<<<64, 256>>>(fcow, fcob, out);
}

// round 16
// speedup vs baseline: 2.1705x; 1.2142x over previous
#include <cuda_runtime.h>
#include <cuda_bf16.h>
#include <cuda_fp16.h>
#include <cooperative_groups.h>
#include <cstdint>
#include <cstddef>

namespace cg = cooperative_groups;

#define HID   256
#define T_SEQ 1024
#define NB    64

// ---------------- scratch (device globals; no allocation) ----------------
__device__ __half g_h1h[(size_t)NB * T_SEQ * 512];    // layer-0 out, fp16
__device__ __half g_w1h[(size_t)2 * 1024 * 512];      // W_ih_l1 fp16
__device__ float g_gx[(size_t)2 * T_SEQ * NB * 1024]; // layer-1 projected gates
__device__ float g_feat[NB * 512];
__device__ float g_y[NB * 256];

__device__ __forceinline__ float sigf(float x) {
    return __fdividef(1.0f, 1.0f + __expf(-x));
}
__device__ __forceinline__ float tanh_fast(float x) {
    float e = __expf(2.0f * x);
    return 1.0f - __fdividef(2.0f, e + 1.0f);
}

// mma.sync m16n8k16 row.col fp16 -> f32 (validated fragment layout)
__device__ __forceinline__ void mma_f16(float* c, const uint32_t* a,
                                        uint32_t b0, uint32_t b1) {
    asm volatile(
        "mma.sync.aligned.m16n8k16.row.col.f32.f16.f16.f32 "
        "{%0,%1,%2,%3}, {%4,%5,%6,%7}, {%8,%9}, {%0,%1,%2,%3};"
        : "+f"(c[0]), "+f"(c[1]), "+f"(c[2]), "+f"(c[3])
        : "r"(a[0]), "r"(a[1]), "r"(a[2]), "r"(a[3]), "r"(b0), "r"(b1));
}

__device__ __forceinline__ void ldsm4(uint32_t* r, uint32_t addr) {
    asm volatile(
        "ldmatrix.sync.aligned.m8n8.x4.shared.b16 {%0,%1,%2,%3}, [%4];"
        : "=r"(r[0]), "=r"(r[1]), "=r"(r[2]), "=r"(r[3]) : "r"(addr));
}

__device__ __forceinline__ uint32_t smem_u32(const void* p) {
    uint32_t a;
    asm("{ .reg .u64 t; cvta.to.shared.u64 t, %1; cvt.u32.u64 %0, t; }" : "=r"(a) : "l"(p));
    return a;
}

__device__ __forceinline__ uint32_t pack_f16(float a, float b) {
    __half2 v = __floats2half2_rn(a, b);
    return *reinterpret_cast<uint32_t*>(&v);
}

#define MBAR_INIT(a, c) \
    asm volatile("mbarrier.init.shared.b64 [%0], %1;" :: "r"(a), "r"((uint32_t)(c)) : "memory")

#define MBAR_WAIT_CL(a, par) do {                                                   \
    uint32_t _m = (a), _p = (par);                                                  \
    asm volatile("{\n\t.reg .pred P1;\n\t"                                          \
        "WLC_%=:\n\t"                                                               \
        "mbarrier.try_wait.parity.acquire.cluster.shared::cta.b64 P1, [%0], %1;\n\t"\
        "@P1 bra.uni WDC_%=;\n\t"                                                   \
        "bra.uni WLC_%=;\n\t"                                                       \
        "WDC_%=:\n\t}" :: "r"(_m), "r"(_p) : "memory");                             \
} while (0)

#define MBAR_ARRIVE_REMOTE(a) \
    asm volatile("mbarrier.arrive.release.cluster.shared::cluster.b64 _, [%0];" \
                 :: "r"(a) : "memory")

#define CLUSTER_ARRIVE() asm volatile("barrier.cluster.arrive.aligned;" ::: "memory")
#define CLUSTER_WAIT()   asm volatile("barrier.cluster.wait.aligned;" ::: "memory")
#define NBAR_SYNC(id)    asm volatile("bar.sync %0, 128;" :: "r"(id) : "memory")

// =====================================================================
// Recurrent LSTM (R12 structure, validated best): both dirs per CTA as
// separate 4-warp groups with per-dir named barriers; 64 CTAs in 8-CTA
// clusters. Warp wg = gate over 32 units: 4 n8 tiles x 16 ks = 64 HMMA.
// A tile M=16: rows 0-7 = h (fp16), rows 8-15 stay ZERO (residual
// dropped; HMMA on zero rows is free). Push exchange: each update
// thread stores its OWN (h0,h1) pair to its own column in all 8 peers
// (R12's validated self-push addressing). Arrive count 32 per dir-buf.
// =====================================================================
template<int LAYER>
__global__ void __launch_bounds__(256, 1) __cluster_dims__(8, 1, 1)
lstm_rec(const float* __restrict__ x, const int* __restrict__ lengths,
         const float* __restrict__ Wih, const float* __restrict__ Whh,
         const float* __restrict__ bih, const float* __restrict__ bhh)
{
    __shared__ __align__(16) uint32_t Ahl[4 * 2112];   // [dir][buf][16*132]
    __shared__ __align__(16) float gates_s[2][8 * 132];
    __shared__ __align__(8)  uint64_t mbars[4];        // [dir][buf]

    const int tid   = threadIdx.x;
    const int w     = tid >> 5;
    const int lane  = tid & 31;
    const int g     = lane >> 2;
    const int t4    = lane & 3;
    uint32_t crank;
    asm("mov.u32 %0, %%cluster_ctarank;" : "=r"(crank));
    const int bg    = blockIdx.x >> 3;     // batch group (8 clusters)
    const int d     = w >> 2;              // direction of this warp group
    const int wg    = w & 3;               // warp-in-group == gate index

    // update-thread identity: 128 threads/group, each owns (batch, unit-pair)
    const int gt     = tid & 127;
    const int b_upd  = gt >> 4;            // 0..7
    const int up     = gt & 15;            // unit pair 0..15
    const int uglob0 = (int)crank * 32 + 2 * up;
    const int bglob  = bg * 8 + b_upd;
    const int L      = lengths[bglob];

    // ---- W_hh fragments (fp16): warp wg covers gate wg, units j*8+g
    uint32_t wf[16][4][2];
    #pragma unroll
    for (int j = 0; j < 4; j++) {
        int grow = d * 1024 + wg * 256 + (int)crank * 32 + j * 8 + g;
        const float* wp = Whh + (size_t)grow * 256;
        #pragma unroll
        for (int ks = 0; ks < 16; ks++) {
            #pragma unroll
            for (int s = 0; s < 2; s++) {
                int kp = ks * 8 + t4 + s * 4;
                float2 wv = *reinterpret_cast<const float2*>(wp + kp * 2);
                wf[ks][j][s] = pack_f16(wv.x, wv.y);
            }
        }
    }

    // ---- layer-0 input projection params (IN = 3) for 2 units
    float wi0[4][3], wi1[4][3], bs0[4], bs1[4];
    if (LAYER == 0) {
        #pragma unroll
        for (int q = 0; q < 4; q++) {
            int r0 = d * 1024 + q * 256 + uglob0;
            wi0[q][0] = Wih[(size_t)r0 * 3 + 0];
            wi0[q][1] = Wih[(size_t)r0 * 3 + 1];
            wi0[q][2] = Wih[(size_t)r0 * 3 + 2];
            bs0[q]    = bih[r0] + bhh[r0];
            int r1 = r0 + 1;
            wi1[q][0] = Wih[(size_t)r1 * 3 + 0];
            wi1[q][1] = Wih[(size_t)r1 * 3 + 1];
            wi1[q][2] = Wih[(size_t)r1 * 3 + 2];
            bs1[q]    = bih[r1] + bhh[r1];
        }
    }

    for (int i = tid; i < 4 * 2112; i += 256) Ahl[i] = 0u;
    const uint32_t mbase = smem_u32(mbars);
    if (tid == 0) {
        #pragma unroll
        for (int i = 0; i < 4; i++) MBAR_INIT(mbase + i * 8, 32);
        asm volatile("fence.mbarrier_init.release.cluster;" ::: "memory");
    }
    __syncthreads();
    CLUSTER_ARRIVE();
    CLUSTER_WAIT();

    // ---- peer addresses
    const uint32_t tbase = smem_u32(Ahl);
    uint32_t peerT[8], peerM[8];
    #pragma unroll
    for (int pe = 0; pe < 8; pe++) {
        asm("mapa.shared::cluster.u32 %0, %1, %2;" : "=r"(peerT[pe]) : "r"(tbase), "r"(pe));
        asm("mapa.shared::cluster.u32 %0, %1, %2;" : "=r"(peerM[pe]) : "r"(mbase), "r"(pe));
    }

    const int lrow  = lane & 15;
    const int lcoff = (lane >> 4) * 4;
    const uint32_t aB0 = tbase + (uint32_t)((d * 2 + 0) * 2112 + lrow * 132 + lcoff) * 4u;
    const uint32_t aB1 = tbase + (uint32_t)((d * 2 + 1) * 2112 + lrow * 132 + lcoff) * 4u;

    // self-push offsets (validated R12 addressing): row = batch, col = crank*16+up
    const uint32_t p_off = (uint32_t)(b_upd * 132 + (int)crank * 16 + up);

    const float* gx_base = g_gx + ((size_t)d * T_SEQ * NB + bglob) * 1024 + uglob0;
    const float* x_base  = x + (size_t)bglob * T_SEQ * 3;

    float c0 = 0.0f, h0 = 0.0f, c1 = 0.0f, h1v = 0.0f;
    int ph0 = 0, ph1 = 0;

    float p0x, p0y, p1x, p1y, p2x, p2y, p3x, p3y;
    float xr0 = 0.f, xr1 = 0.f, xr2 = 0.f;
    if (LAYER == 1) {
        float2 v0 = *reinterpret_cast<const float2*>(gx_base);
        float2 v1 = *reinterpret_cast<const float2*>(gx_base + 256);
        float2 v2 = *reinterpret_cast<const float2*>(gx_base + 512);
        float2 v3 = *reinterpret_cast<const float2*>(gx_base + 768);
        p0x = v0.x; p0y = v0.y; p1x = v1.x; p1y = v1.y;
        p2x = v2.x; p2y = v2.y; p3x = v3.x; p3y = v3.y;
    } else {
        int teff0 = (d == 0) ? 0 : ((L > 0) ? (L - 1) : 0);
        const float* xp = x_base + (size_t)teff0 * 3;
        xr0 = xp[0]; xr1 = xp[1]; xr2 = xp[2];
    }

    for (int t = 0; t < T_SEQ; t++) {
        const bool m = (t < L);

        if (LAYER == 0) {
            p0x = bs0[0] + wi0[0][0]*xr0 + wi0[0][1]*xr1 + wi0[0][2]*xr2;
            p1x = bs0[1] + wi0[1][0]*xr0 + wi0[1][1]*xr1 + wi0[1][2]*xr2;
            p2x = bs0[2] + wi0[2][0]*xr0 + wi0[2][1]*xr1 + wi0[2][2]*xr2;
            p3x = bs0[3] + wi0[3][0]*xr0 + wi0[3][1]*xr1 + wi0[3][2]*xr2;
            p0y = bs1[0] + wi1[0][0]*xr0 + wi1[0][1]*xr1 + wi1[0][2]*xr2;
            p1y = bs1[1] + wi1[1][0]*xr0 + wi1[1][1]*xr1 + wi1[1][2]*xr2;
            p2y = bs1[2] + wi1[2][0]*xr0 + wi1[2][1]*xr1 + wi1[2][2]*xr2;
            p3y = bs1[3] + wi1[3][0]*xr0 + wi1[3][1]*xr1 + wi1[3][2]*xr2;
        }

        // ---- wait for this step's A tile of OWN dir (t=0 reads zeros)
        const int buf = t & 1;
        if (t > 0) {
            if (buf) { MBAR_WAIT_CL(mbase + (uint32_t)(d * 2 + 1) * 8u, ph1); ph1 ^= 1; }
            else     { MBAR_WAIT_CL(mbase + (uint32_t)(d * 2 + 0) * 8u, ph0); ph0 ^= 1; }
        }
        const uint32_t aBase = buf ? aB1 : aB0;

        // ---- matvec: 4 independent chains (4 n8 tiles), 64 HMMA/warp
        float acc[4][4];
        #pragma unroll
        for (int j = 0; j < 4; j++) {
            acc[j][0] = 0.f; acc[j][1] = 0.f; acc[j][2] = 0.f; acc[j][3] = 0.f;
        }
        #pragma unroll
        for (int ks = 0; ks < 16; ks++) {
            uint32_t a[4];
            ldsm4(a, aBase + (uint32_t)ks * 32u);
            #pragma unroll
            for (int j = 0; j < 4; j++)
                mma_f16(acc[j], a, wf[ks][j][0], wf[ks][j][1]);
        }

        // ---- dump gates (rows 8-15 zero => acc[j][2..3] = 0, summed anyway)
        #pragma unroll
        for (int j = 0; j < 4; j++)
            *reinterpret_cast<float2*>(
                &gates_s[d][g * 132 + wg * 32 + j * 8 + 2 * t4]) =
                make_float2(acc[j][0] + acc[j][2], acc[j][1] + acc[j][3]);
        NBAR_SYNC(d + 1);

        // ---- update 2 units: gates at rlocal = gate*32 + 2up (+1)
        float2 G0 = *reinterpret_cast<const float2*>(&gates_s[d][b_upd * 132 +       2 * up]);
        float2 G1 = *reinterpret_cast<const float2*>(&gates_s[d][b_upd * 132 +  32 + 2 * up]);
        float2 G2 = *reinterpret_cast<const float2*>(&gates_s[d][b_upd * 132 +  64 + 2 * up]);
        float2 G3 = *reinterpret_cast<const float2*>(&gates_s[d][b_upd * 132 +  96 + 2 * up]);
        {
            float ig = sigf(p0x + G0.x), fg = sigf(p1x + G1.x);
            float gg = tanh_fast(p2x + G2.x), og = sigf(p3x + G3.x);
            float cn = fmaf(fg, c0, ig * gg);
            float hn = og * tanh_fast(cn);
            if (m) { c0 = cn; h0 = hn; }
        }
        {
            float ig = sigf(p0y + G0.y), fg = sigf(p1y + G1.y);
            float gg = tanh_fast(p2y + G2.y), og = sigf(p3y + G3.y);
            float cn = fmaf(fg, c1, ig * gg);
            float hn = og * tanh_fast(cn);
            if (m) { c1 = cn; h1v = hn; }
        }

        // ---- self-push own fp16 pair (hi rows only) into all peers' tile[d][nb]
        if (t + 1 < T_SEQ) {
            const uint32_t nb = (uint32_t)((t + 1) & 1);
            uint32_t hi = pack_f16(h0, h1v);
            const uint32_t off =
                (((uint32_t)(d * 2) + nb) * 2112u + p_off) * 4u;
            #pragma unroll
            for (int pe = 0; pe < 8; pe++)
                asm volatile("st.shared::cluster.b32 [%0], %1;"
                             :: "r"(peerT[pe] + off), "r"(hi) : "memory");
            __syncwarp();
            if (lane < 8)
                MBAR_ARRIVE_REMOTE(peerM[lane] + ((uint32_t)(d * 2) + nb) * 8u);
        }

        // ---- next-step input prefetch (long cover)
        if (LAYER == 1) {
            int tn = (t + 1 < T_SEQ) ? t + 1 : t;
            const float* gp = gx_base + (size_t)tn * NB * 1024;
            float2 v0 = *reinterpret_cast<const float2*>(gp);
            float2 v1 = *reinterpret_cast<const float2*>(gp + 256);
            float2 v2 = *reinterpret_cast<const float2*>(gp + 512);
            float2 v3 = *reinterpret_cast<const float2*>(gp + 768);
            p0x = v0.x; p0y = v0.y; p1x = v1.x; p1y = v1.y;
            p2x = v2.x; p2y = v2.y; p3x = v3.x; p3y = v3.y;
        } else {
            int tn = (t + 1 < T_SEQ) ? t + 1 : t;
            bool mn = (tn < L);
            int teffn = (d == 0) ? tn : (mn ? (L - 1 - tn) : tn);
            const float* xp = x_base + (size_t)teffn * 3;
            xr0 = xp[0]; xr1 = xp[1]; xr2 = xp[2];
        }

        // ---- global stores (off critical path)
        if (LAYER == 0) {
            int pos = (d == 0) ? t : (m ? (L - 1 - t) : t);
            float v0 = m ? h0 : 0.0f, v1 = m ? h1v : 0.0f;
            *reinterpret_cast<__half2*>(
                &g_h1h[((size_t)bglob * T_SEQ + pos) * 512 + d * 256 + uglob0]) =
                __floats2half2_rn(v0, v1);
        } else if (d == 1 && t == 0) {
            g_feat[bglob * 512 + 256 + uglob0]     = h0;
            g_feat[bglob * 512 + 256 + uglob0 + 1] = h1v;
        }
    }

    if (LAYER == 1 && d == 0) {
        g_feat[bglob * 512 + uglob0]     = h0;
        g_feat[bglob * 512 + uglob0 + 1] = h1v;
    }

    CLUSTER_ARRIVE();
    CLUSTER_WAIT();
}

// =====================================================================
// W_ih_l1 fp32 -> fp16
// =====================================================================
__global__ void __launch_bounds__(256) conv_w1(const float* __restrict__ Wih)
{
    size_t i = (size_t)blockIdx.x * 1024 + threadIdx.x * 4;
    float4 v = *reinterpret_cast<const float4*>(Wih + i);
    g_w1h[i + 0] = __float2half_rn(v.x);
    g_w1h[i + 1] = __float2half_rn(v.y);
    g_w1h[i + 2] = __float2half_rn(v.z);
    g_w1h[i + 3] = __float2half_rn(v.w);
}

// =====================================================================
// Layer-1 input projection via fp16 HMMA (unchanged, validated).
// =====================================================================
__global__ void __launch_bounds__(256) gx_mma(
    const int* __restrict__ lengths,
    const float* __restrict__ bih, const float* __restrict__ bhh)
{
    __shared__ __align__(16) uint32_t Ax[64 * 20];
    __shared__ __align__(16) uint32_t Bx[128 * 20];
    __shared__ float bias_s[128];

    const int tid  = threadIdx.x;
    const int wid  = tid >> 5;
    const int lane = tid & 31;
    const int g    = lane >> 2;
    const int t4   = lane & 3;
    const int n0   = blockIdx.x * 128;
    const int t    = blockIdx.y;
    const int dir  = blockIdx.z;

    const int m0 = (wid & 1) * 32;
    const int nw = (wid >> 1) * 32;

    const int ar = tid >> 2, ac = tid & 3;
    const int br = tid >> 1, bc = tid & 1;
    if (tid < 128) bias_s[tid] = bih[dir * 1024 + n0 + tid] + bhh[dir * 1024 + n0 + tid];

    const int La = lengths[ar];
    const int teff = dir ? ((t < La) ? (La - 1 - t) : t) : t;
    const uint4* a_p = (const uint4*)(g_h1h + ((size_t)ar * T_SEQ + teff) * 512) + ac;
    const uint4* b_p = (const uint4*)(g_w1h + ((size_t)(dir * 1024 + n0 + br)) * 512) + bc * 2;

    float acc[2][4][4];
    #pragma unroll
    for (int i = 0; i < 2; i++)
        #pragma unroll
        for (int j = 0; j < 4; j++)
            #pragma unroll
            for (int k = 0; k < 4; k++) acc[i][j][k] = 0.0f;

    uint4 va  = __ldg(a_p);
    uint4 vb0 = __ldg(b_p), vb1 = __ldg(b_p + 1);

    for (int kc = 0; kc < 16; kc++) {
        *reinterpret_cast<uint4*>(&Ax[ar * 20 + ac * 4]) = va;
        *reinterpret_cast<uint4*>(&Bx[br * 20 + bc * 8])     = vb0;
        *reinterpret_cast<uint4*>(&Bx[br * 20 + bc * 8 + 4]) = vb1;
        __syncthreads();

        if (kc + 1 < 16) {
            va  = __ldg(a_p + (kc + 1) * 4);
            vb0 = __ldg(b_p + (kc + 1) * 4);
            vb1 = __ldg(b_p + (kc + 1) * 4 + 1);
        }

        #pragma unroll
        for (int ks = 0; ks < 2; ks++) {
            uint32_t a[2][4];
            #pragma unroll
            for (int mf = 0; mf < 2; mf++) {
                int r = m0 + mf * 16 + g;
                a[mf][0] = Ax[r * 20 + ks * 8 + t4];
                a[mf][1] = Ax[(r + 8) * 20 + ks * 8 + t4];
                a[mf][2] = Ax[r * 20 + ks * 8 + t4 + 4];
                a[mf][3] = Ax[(r + 8) * 20 + ks * 8 + t4 + 4];
            }
            #pragma unroll
            for (int nf = 0; nf < 4; nf++) {
                int rn = nw + nf * 8 + g;
                uint32_t b0 = Bx[rn * 20 + ks * 8 + t4];
                uint32_t b1 = Bx[rn * 20 + ks * 8 + t4 + 4];
                mma_f16(acc[0][nf], a[0], b0, b1);
                mma_f16(acc[1][nf], a[1], b0, b1);
            }
        }
        __syncthreads();
    }

    float* gxp = g_gx + ((size_t)(dir * T_SEQ + t) * NB) * 1024 + n0;
    #pragma unroll
    for (int mf = 0; mf < 2; mf++) {
        int bi = m0 + mf * 16 + g;
        #pragma unroll
        for (int nf = 0; nf < 4; nf++) {
            int nn = nw + nf * 8 + t4 * 2;
            float bv0 = bias_s[nn], bv1 = bias_s[nn + 1];
            float2 v0 = make_float2(acc[mf][nf][0] + bv0, acc[mf][nf][1] + bv1);
            float2 v1 = make_float2(acc[mf][nf][2] + bv0, acc[mf][nf][3] + bv1);
            *reinterpret_cast<float2*>(gxp + (size_t)bi * 1024 + nn)       = v0;
            *reinterpret_cast<float2*>(gxp + (size_t)(bi + 8) * 1024 + nn) = v1;
        }
    }
}

// =====================================================================
// Head
// =====================================================================
__global__ void __launch_bounds__(256) head_fc1(const float* __restrict__ fc1_w,
                                                const float* __restrict__ fc1_b)
{
    __shared__ __align__(16) float fs[512];
    int b = blockIdx.x, n = threadIdx.x;
    for (int i = n; i < 512; i += 256) fs[i] = g_feat[b * 512 + i];
    __syncthreads();
    const float4* wp = reinterpret_cast<const float4*>(fc1_w + (size_t)n * 512);
    const float4* fp = reinterpret_cast<const float4*>(fs);
    float acc = fc1_b[n];
    #pragma unroll 4
    for (int k = 0; k < 128; k++) {
        float4 w4 = __ldg(wp + k);
        float4 f4 = fp[k];
        acc += w4.x * f4.x + w4.y * f4.y + w4.z * f4.z + w4.w * f4.w;
    }
    g_y[b * 256 + n] = fmaxf(acc, 0.0f);
}

__global__ void head_bn(const float* __restrict__ gamma, const float* __restrict__ beta)
{
    int n = threadIdx.x;
    float s = 0.0f, s2 = 0.0f;
    for (int b = 0; b < 64; b++) {
        float v = g_y[b * 256 + n];
        s += v; s2 += v * v;
    }
    float mean = s * 0.015625f;
    float var  = s2 * 0.015625f - mean * mean;
    float inv  = rsqrtf(var + 1e-5f);
    float ga = gamma[n] * inv, be = beta[n];
    for (int b = 0; b < 64; b++)
        g_y[b * 256 + n] = (g_y[b * 256 + n] - mean) * ga + be;
}

__global__ void __launch_bounds__(256) head_out(const float* __restrict__ W,
                                                const float* __restrict__ bias,
                                                float* __restrict__ out)
{
    __shared__ __align__(16) float ys[256];
    int b = blockIdx.x;
    ys[threadIdx.x] = g_y[b * 256 + threadIdx.x];
    __syncthreads();
    int o = threadIdx.x;
    if (o < 196) {
        const float4* wp = reinterpret_cast<const float4*>(W + (size_t)o * 256);
        const float4* yp = reinterpret_cast<const float4*>(ys);
        float acc = bias[o];
        #pragma unroll 4
        for (int k = 0; k < 64; k++) {
            float4 w4 = __ldg(wp + k);
            float4 y4 = yp[k];
            acc += w4.x * y4.x + w4.y * y4.y + w4.z * y4.z + w4.w * y4.w;
        }
        out[(size_t)b * 196 + o] = acc;
    }
}

// =====================================================================
extern "C" void kernel_launch(void* const* d_in, const int* in_sizes, int n_in,
                              void* d_out, int out_size)
{
    const float* x       = (const float*)d_in[0];
    const int*   lengths = (const int*)  d_in[1];
    const float* Wih0    = (const float*)d_in[2];
    const float* Whh0    = (const float*)d_in[3];
    const float* bih0    = (const float*)d_in[4];
    const float* bhh0    = (const float*)d_in[5];
    const float* Wih1    = (const float*)d_in[6];
    const float* Whh1    = (const float*)d_in[7];
    const float* bih1    = (const float*)d_in[8];
    const float* bhh1    = (const float*)d_in[9];
    const float* fc1_w   = (const float*)d_in[10];
    const float* fc1_b   = (const float*)d_in[11];
    const float* gamma   = (const float*)d_in[12];
    const float* beta    = (const float*)d_in[13];
    const float* fcow    = (const float*)d_in[14];
    const float* fcob    = (const float*)d_in[15];
    float* out = (float*)d_out;

    conv_w1<<<1024, 256>>>(Wih1);
    lstm_rec<0><<<64, 256>>>(x, lengths, Wih0, Whh0, bih0, bhh0);
    gx_mma<<<dim3(8, 1024, 2), 256>>>(lengths, bih1, bhh1);
    lstm_rec<1><<<64, 256>>>(x, lengths, Wih1, Whh1, bih1, bhh1);
    head_fc1<<<64, 256>>>(fc1_w, fc1_b);
    head_bn<<<1, 256>>>(gamma, beta);
    head_out<<<64, 256>>>(fcow, fcob, out);
}

// round 17
// speedup vs baseline: 2.5302x; 1.1657x over previous
#include <cuda_runtime.h>
#include <cuda_bf16.h>
#include <cuda_fp16.h>
#include <cooperative_groups.h>
#include <cstdint>
#include <cstddef>

namespace cg = cooperative_groups;

#define HID   256
#define T_SEQ 1024
#define NB    64

// ---------------- scratch (device globals; no allocation) ----------------
__device__ __half g_h1h[(size_t)NB * T_SEQ * 512];    // layer-0 out, fp16
__device__ __half g_w1h[(size_t)2 * 1024 * 512];      // W_ih_l1 fp16
__device__ float g_gx[(size_t)2 * T_SEQ * NB * 1024]; // layer-1 projected gates
__device__ float g_feat[NB * 512];
__device__ float g_y[NB * 256];

__device__ __forceinline__ float sigf(float x) {
    return __fdividef(1.0f, 1.0f + __expf(-x));
}
__device__ __forceinline__ float tanh_fast(float x) {
    float e = __expf(2.0f * x);
    return 1.0f - __fdividef(2.0f, e + 1.0f);
}

// mma.sync m16n8k16 row.col fp16 -> f32 (validated fragment layout)
__device__ __forceinline__ void mma_f16(float* c, const uint32_t* a,
                                        uint32_t b0, uint32_t b1) {
    asm volatile(
        "mma.sync.aligned.m16n8k16.row.col.f32.f16.f16.f32 "
        "{%0,%1,%2,%3}, {%4,%5,%6,%7}, {%8,%9}, {%0,%1,%2,%3};"
        : "+f"(c[0]), "+f"(c[1]), "+f"(c[2]), "+f"(c[3])
        : "r"(a[0]), "r"(a[1]), "r"(a[2]), "r"(a[3]), "r"(b0), "r"(b1));
}

__device__ __forceinline__ uint32_t smem_u32(const void* p) {
    uint32_t a;
    asm("{ .reg .u64 t; cvta.to.shared.u64 t, %1; cvt.u32.u64 %0, t; }" : "=r"(a) : "l"(p));
    return a;
}

__device__ __forceinline__ uint32_t pack_f16(float a, float b) {
    __half2 v = __floats2half2_rn(a, b);
    return *reinterpret_cast<uint32_t*>(&v);
}

#define MBAR_INIT(a, c) \
    asm volatile("mbarrier.init.shared.b64 [%0], %1;" :: "r"(a), "r"((uint32_t)(c)) : "memory")

#define MBAR_WAIT_CL(a, par) do {                                                   \
    uint32_t _m = (a), _p = (par);                                                  \
    asm volatile("{\n\t.reg .pred P1;\n\t"                                          \
        "WLC_%=:\n\t"                                                               \
        "mbarrier.try_wait.parity.acquire.cluster.shared::cta.b64 P1, [%0], %1;\n\t"\
        "@P1 bra.uni WDC_%=;\n\t"                                                   \
        "bra.uni WLC_%=;\n\t"                                                       \
        "WDC_%=:\n\t}" :: "r"(_m), "r"(_p) : "memory");                             \
} while (0)

#define MBAR_ARRIVE_REMOTE(a) \
    asm volatile("mbarrier.arrive.release.cluster.shared::cluster.b64 _, [%0];" \
                 :: "r"(a) : "memory")

#define CLUSTER_ARRIVE() asm volatile("barrier.cluster.arrive.aligned;" ::: "memory")
#define CLUSTER_WAIT()   asm volatile("barrier.cluster.wait.aligned;" ::: "memory")
#define NBAR_SYNC(id)    asm volatile("bar.sync %0, 128;" :: "r"(id) : "memory")

// =====================================================================
// Recurrent LSTM, OPERAND-SWAPPED HMMA: W = A operand (m16 = gate-rows,
// register-resident), h = B operand (n8 = 8 batches, zero M waste).
// R12/R16 structure otherwise: both dirs per CTA as separate 4-warp
// groups + per-dir named barriers; 64 CTAs in 8-CTA clusters. Warp wg =
// gate wg over 32 units = 2 m16-tiles x 16 k-blocks = 32 HMMA/step.
// h tile per dir: 8 batches x 132 u32 kpairs, double-buffered.
// Self-push exchange (validated): each update thread stores its own
// fp16 (h0,h1) pair to its own column in all 8 peers; arrive count 32.
// =====================================================================
template<int LAYER>
__global__ void __launch_bounds__(256, 1) __cluster_dims__(8, 1, 1)
lstm_rec(const float* __restrict__ x, const int* __restrict__ lengths,
         const float* __restrict__ Wih, const float* __restrict__ Whh,
         const float* __restrict__ bih, const float* __restrict__ bhh)
{
    __shared__ __align__(16) uint32_t Ahl[4 * 1056];   // [dir][buf][8*132]
    __shared__ __align__(16) float gates_s[2][8 * 132];
    __shared__ __align__(8)  uint64_t mbars[4];        // [dir][buf]

    const int tid   = threadIdx.x;
    const int w     = tid >> 5;
    const int lane  = tid & 31;
    const int g     = lane >> 2;
    const int t4    = lane & 3;
    uint32_t crank;
    asm("mov.u32 %0, %%cluster_ctarank;" : "=r"(crank));
    const int bg    = blockIdx.x >> 3;     // batch group (8 clusters)
    const int d     = w >> 2;              // direction of this warp group
    const int wg    = w & 3;               // warp-in-group == gate index

    // update-thread identity: 128 threads/group, each owns (batch, unit-pair)
    const int gt     = tid & 127;
    const int b_upd  = gt >> 4;            // 0..7
    const int up     = gt & 15;            // unit pair 0..15
    const int uglob0 = (int)crank * 32 + 2 * up;
    const int bglob  = bg * 8 + b_upd;
    const int L      = lengths[bglob];

    // ---- W_hh as A-operand fragments (fp16): wf[ks][tile j][4]
    //      tile j rows = units [j*16, j*16+16); thread reads rows g, g+8
    uint32_t wf[16][2][4];
    #pragma unroll
    for (int j = 0; j < 2; j++) {
        int grow_g  = d * 1024 + wg * 256 + (int)crank * 32 + j * 16 + g;
        int grow_g8 = grow_g + 8;
        const float* wpg  = Whh + (size_t)grow_g  * 256;
        const float* wpg8 = Whh + (size_t)grow_g8 * 256;
        #pragma unroll
        for (int ks = 0; ks < 16; ks++) {
            float2 v0 = *reinterpret_cast<const float2*>(wpg  + (ks * 8 + t4) * 2);
            float2 v1 = *reinterpret_cast<const float2*>(wpg8 + (ks * 8 + t4) * 2);
            float2 v2 = *reinterpret_cast<const float2*>(wpg  + (ks * 8 + t4 + 4) * 2);
            float2 v3 = *reinterpret_cast<const float2*>(wpg8 + (ks * 8 + t4 + 4) * 2);
            wf[ks][j][0] = pack_f16(v0.x, v0.y);
            wf[ks][j][1] = pack_f16(v1.x, v1.y);
            wf[ks][j][2] = pack_f16(v2.x, v2.y);
            wf[ks][j][3] = pack_f16(v3.x, v3.y);
        }
    }

    // ---- layer-0 input projection params (IN = 3) for 2 units
    float wi0[4][3], wi1[4][3], bs0[4], bs1[4];
    if (LAYER == 0) {
        #pragma unroll
        for (int q = 0; q < 4; q++) {
            int r0 = d * 1024 + q * 256 + uglob0;
            wi0[q][0] = Wih[(size_t)r0 * 3 + 0];
            wi0[q][1] = Wih[(size_t)r0 * 3 + 1];
            wi0[q][2] = Wih[(size_t)r0 * 3 + 2];
            bs0[q]    = bih[r0] + bhh[r0];
            int r1 = r0 + 1;
            wi1[q][0] = Wih[(size_t)r1 * 3 + 0];
            wi1[q][1] = Wih[(size_t)r1 * 3 + 1];
            wi1[q][2] = Wih[(size_t)r1 * 3 + 2];
            bs1[q]    = bih[r1] + bhh[r1];
        }
    }

    for (int i = tid; i < 4 * 1056; i += 256) Ahl[i] = 0u;
    const uint32_t mbase = smem_u32(mbars);
    if (tid == 0) {
        #pragma unroll
        for (int i = 0; i < 4; i++) MBAR_INIT(mbase + i * 8, 32);
        asm volatile("fence.mbarrier_init.release.cluster;" ::: "memory");
    }
    __syncthreads();
    CLUSTER_ARRIVE();
    CLUSTER_WAIT();

    // ---- peer addresses
    const uint32_t tbase = smem_u32(Ahl);
    uint32_t peerT[8], peerM[8];
    #pragma unroll
    for (int pe = 0; pe < 8; pe++) {
        asm("mapa.shared::cluster.u32 %0, %1, %2;" : "=r"(peerT[pe]) : "r"(tbase), "r"(pe));
        asm("mapa.shared::cluster.u32 %0, %1, %2;" : "=r"(peerM[pe]) : "r"(mbase), "r"(pe));
    }

    // B-fragment per-lane base: row g (batch), kpair t4
    const uint32_t hB0 = tbase + (uint32_t)((d * 2 + 0) * 1056 + g * 132 + t4) * 4u;
    const uint32_t hB1 = tbase + (uint32_t)((d * 2 + 1) * 1056 + g * 132 + t4) * 4u;

    // self-push offset: row = batch, col = crank*16 + up
    const uint32_t p_off = (uint32_t)(b_upd * 132 + (int)crank * 16 + up);

    const float* gx_base = g_gx + ((size_t)d * T_SEQ * NB + bglob) * 1024 + uglob0;
    const float* x_base  = x + (size_t)bglob * T_SEQ * 3;

    float c0 = 0.0f, h0 = 0.0f, c1 = 0.0f, h1v = 0.0f;
    int ph0 = 0, ph1 = 0;

    float p0x, p0y, p1x, p1y, p2x, p2y, p3x, p3y;
    float xr0 = 0.f, xr1 = 0.f, xr2 = 0.f;
    if (LAYER == 1) {
        float2 v0 = *reinterpret_cast<const float2*>(gx_base);
        float2 v1 = *reinterpret_cast<const float2*>(gx_base + 256);
        float2 v2 = *reinterpret_cast<const float2*>(gx_base + 512);
        float2 v3 = *reinterpret_cast<const float2*>(gx_base + 768);
        p0x = v0.x; p0y = v0.y; p1x = v1.x; p1y = v1.y;
        p2x = v2.x; p2y = v2.y; p3x = v3.x; p3y = v3.y;
    } else {
        int teff0 = (d == 0) ? 0 : ((L > 0) ? (L - 1) : 0);
        const float* xp = x_base + (size_t)teff0 * 3;
        xr0 = xp[0]; xr1 = xp[1]; xr2 = xp[2];
    }

    for (int t = 0; t < T_SEQ; t++) {
        const bool m = (t < L);

        if (LAYER == 0) {
            p0x = bs0[0] + wi0[0][0]*xr0 + wi0[0][1]*xr1 + wi0[0][2]*xr2;
            p1x = bs0[1] + wi0[1][0]*xr0 + wi0[1][1]*xr1 + wi0[1][2]*xr2;
            p2x = bs0[2] + wi0[2][0]*xr0 + wi0[2][1]*xr1 + wi0[2][2]*xr2;
            p3x = bs0[3] + wi0[3][0]*xr0 + wi0[3][1]*xr1 + wi0[3][2]*xr2;
            p0y = bs1[0] + wi1[0][0]*xr0 + wi1[0][1]*xr1 + wi1[0][2]*xr2;
            p1y = bs1[1] + wi1[1][0]*xr0 + wi1[1][1]*xr1 + wi1[1][2]*xr2;
            p2y = bs1[2] + wi1[2][0]*xr0 + wi1[2][1]*xr1 + wi1[2][2]*xr2;
            p3y = bs1[3] + wi1[3][0]*xr0 + wi1[3][1]*xr1 + wi1[3][2]*xr2;
        }

        // ---- wait for this step's h tile of OWN dir (t=0 reads zeros)
        const int buf = t & 1;
        if (t > 0) {
            if (buf) { MBAR_WAIT_CL(mbase + (uint32_t)(d * 2 + 1) * 8u, ph1); ph1 ^= 1; }
            else     { MBAR_WAIT_CL(mbase + (uint32_t)(d * 2 + 0) * 8u, ph0); ph0 ^= 1; }
        }
        const uint32_t hBase = buf ? hB1 : hB0;

        // ---- matvec: W(A-reg) x h(B-smem), 2 m16 tiles x 16 ks = 32 HMMA
        float acc[2][4];
        #pragma unroll
        for (int j = 0; j < 2; j++) {
            acc[j][0] = 0.f; acc[j][1] = 0.f; acc[j][2] = 0.f; acc[j][3] = 0.f;
        }
        #pragma unroll
        for (int ks = 0; ks < 16; ks++) {
            uint32_t b0, b1;
            asm volatile("ld.shared.b32 %0, [%1];" : "=r"(b0)
                         : "r"(hBase + (uint32_t)(ks * 8) * 4u));
            asm volatile("ld.shared.b32 %0, [%1];" : "=r"(b1)
                         : "r"(hBase + (uint32_t)(ks * 8 + 4) * 4u));
            mma_f16(acc[0], wf[ks][0], b0, b1);
            mma_f16(acc[1], wf[ks][1], b0, b1);
        }

        // ---- dump gates: D[row=gate-unit][col=batch]
        //      c0=D[g][2t4], c1=D[g][2t4+1], c2=D[g+8][2t4], c3=D[g+8][2t4+1]
        #pragma unroll
        for (int j = 0; j < 2; j++) {
            int rl = wg * 32 + j * 16;
            gates_s[d][(2 * t4)     * 132 + rl + g]     = acc[j][0];
            gates_s[d][(2 * t4 + 1) * 132 + rl + g]     = acc[j][1];
            gates_s[d][(2 * t4)     * 132 + rl + g + 8] = acc[j][2];
            gates_s[d][(2 * t4 + 1) * 132 + rl + g + 8] = acc[j][3];
        }
        NBAR_SYNC(d + 1);

        // ---- update 2 units: gates at [batch][gate*32 + 2up (+1)]
        float2 G0 = *reinterpret_cast<const float2*>(&gates_s[d][b_upd * 132 +       2 * up]);
        float2 G1 = *reinterpret_cast<const float2*>(&gates_s[d][b_upd * 132 +  32 + 2 * up]);
        float2 G2 = *reinterpret_cast<const float2*>(&gates_s[d][b_upd * 132 +  64 + 2 * up]);
        float2 G3 = *reinterpret_cast<const float2*>(&gates_s[d][b_upd * 132 +  96 + 2 * up]);
        {
            float ig = sigf(p0x + G0.x), fg = sigf(p1x + G1.x);
            float gg = tanh_fast(p2x + G2.x), og = sigf(p3x + G3.x);
            float cn = fmaf(fg, c0, ig * gg);
            float hn = og * tanh_fast(cn);
            if (m) { c0 = cn; h0 = hn; }
        }
        {
            float ig = sigf(p0y + G0.y), fg = sigf(p1y + G1.y);
            float gg = tanh_fast(p2y + G2.y), og = sigf(p3y + G3.y);
            float cn = fmaf(fg, c1, ig * gg);
            float hn = og * tanh_fast(cn);
            if (m) { c1 = cn; h1v = hn; }
        }

        // ---- self-push own fp16 pair into all peers' tile[d][nb]
        if (t + 1 < T_SEQ) {
            const uint32_t nb = (uint32_t)((t + 1) & 1);
            uint32_t hi = pack_f16(h0, h1v);
            const uint32_t off =
                (((uint32_t)(d * 2) + nb) * 1056u + p_off) * 4u;
            #pragma unroll
            for (int pe = 0; pe < 8; pe++)
                asm volatile("st.shared::cluster.b32 [%0], %1;"
                             :: "r"(peerT[pe] + off), "r"(hi) : "memory");
            __syncwarp();
            if (lane < 8)
                MBAR_ARRIVE_REMOTE(peerM[lane] + ((uint32_t)(d * 2) + nb) * 8u);
        }

        // ---- next-step input prefetch (long cover)
        if (LAYER == 1) {
            int tn = (t + 1 < T_SEQ) ? t + 1 : t;
            const float* gp = gx_base + (size_t)tn * NB * 1024;
            float2 v0 = *reinterpret_cast<const float2*>(gp);
            float2 v1 = *reinterpret_cast<const float2*>(gp + 256);
            float2 v2 = *reinterpret_cast<const float2*>(gp + 512);
            float2 v3 = *reinterpret_cast<const float2*>(gp + 768);
            p0x = v0.x; p0y = v0.y; p1x = v1.x; p1y = v1.y;
            p2x = v2.x; p2y = v2.y; p3x = v3.x; p3y = v3.y;
        } else {
            int tn = (t + 1 < T_SEQ) ? t + 1 : t;
            bool mn = (tn < L);
            int teffn = (d == 0) ? tn : (mn ? (L - 1 - tn) : tn);
            const float* xp = x_base + (size_t)teffn * 3;
            xr0 = xp[0]; xr1 = xp[1]; xr2 = xp[2];
        }

        // ---- global stores (off critical path)
        if (LAYER == 0) {
            int pos = (d == 0) ? t : (m ? (L - 1 - t) : t);
            float v0 = m ? h0 : 0.0f, v1 = m ? h1v : 0.0f;
            *reinterpret_cast<__half2*>(
                &g_h1h[((size_t)bglob * T_SEQ + pos) * 512 + d * 256 + uglob0]) =
                __floats2half2_rn(v0, v1);
        } else if (d == 1 && t == 0) {
            g_feat[bglob * 512 + 256 + uglob0]     = h0;
            g_feat[bglob * 512 + 256 + uglob0 + 1] = h1v;
        }
    }

    if (LAYER == 1 && d == 0) {
        g_feat[bglob * 512 + uglob0]     = h0;
        g_feat[bglob * 512 + uglob0 + 1] = h1v;
    }

    CLUSTER_ARRIVE();
    CLUSTER_WAIT();
}

// =====================================================================
// W_ih_l1 fp32 -> fp16
// =====================================================================
__global__ void __launch_bounds__(256) conv_w1(const float* __restrict__ Wih)
{
    size_t i = (size_t)blockIdx.x * 1024 + threadIdx.x * 4;
    float4 v = *reinterpret_cast<const float4*>(Wih + i);
    g_w1h[i + 0] = __float2half_rn(v.x);
    g_w1h[i + 1] = __float2half_rn(v.y);
    g_w1h[i + 2] = __float2half_rn(v.z);
    g_w1h[i + 3] = __float2half_rn(v.w);
}

// =====================================================================
// Layer-1 input projection via fp16 HMMA (unchanged, validated).
// =====================================================================
__device__ __forceinline__ void ldsm4(uint32_t* r, uint32_t addr) {
    asm volatile(
        "ldmatrix.sync.aligned.m8n8.x4.shared.b16 {%0,%1,%2,%3}, [%4];"
        : "=r"(r[0]), "=r"(r[1]), "=r"(r[2]), "=r"(r[3]) : "r"(addr));
}

__global__ void __launch_bounds__(256) gx_mma(
    const int* __restrict__ lengths,
    const float* __restrict__ bih, const float* __restrict__ bhh)
{
    __shared__ __align__(16) uint32_t Ax[64 * 20];
    __shared__ __align__(16) uint32_t Bx[128 * 20];
    __shared__ float bias_s[128];

    const int tid  = threadIdx.x;
    const int wid  = tid >> 5;
    const int lane = tid & 31;
    const int g    = lane >> 2;
    const int t4   = lane & 3;
    const int n0   = blockIdx.x * 128;
    const int t    = blockIdx.y;
    const int dir  = blockIdx.z;

    const int m0 = (wid & 1) * 32;
    const int nw = (wid >> 1) * 32;

    const int ar = tid >> 2, ac = tid & 3;
    const int br = tid >> 1, bc = tid & 1;
    if (tid < 128) bias_s[tid] = bih[dir * 1024 + n0 + tid] + bhh[dir * 1024 + n0 + tid];

    const int La = lengths[ar];
    const int teff = dir ? ((t < La) ? (La - 1 - t) : t) : t;
    const uint4* a_p = (const uint4*)(g_h1h + ((size_t)ar * T_SEQ + teff) * 512) + ac;
    const uint4* b_p = (const uint4*)(g_w1h + ((size_t)(dir * 1024 + n0 + br)) * 512) + bc * 2;

    float acc[2][4][4];
    #pragma unroll
    for (int i = 0; i < 2; i++)
        #pragma unroll
        for (int j = 0; j < 4; j++)
            #pragma unroll
            for (int k = 0; k < 4; k++) acc[i][j][k] = 0.0f;

    uint4 va  = __ldg(a_p);
    uint4 vb0 = __ldg(b_p), vb1 = __ldg(b_p + 1);

    for (int kc = 0; kc < 16; kc++) {
        *reinterpret_cast<uint4*>(&Ax[ar * 20 + ac * 4]) = va;
        *reinterpret_cast<uint4*>(&Bx[br * 20 + bc * 8])     = vb0;
        *reinterpret_cast<uint4*>(&Bx[br * 20 + bc * 8 + 4]) = vb1;
        __syncthreads();

        if (kc + 1 < 16) {
            va  = __ldg(a_p + (kc + 1) * 4);
            vb0 = __ldg(b_p + (kc + 1) * 4);
            vb1 = __ldg(b_p + (kc + 1) * 4 + 1);
        }

        #pragma unroll
        for (int ks = 0; ks < 2; ks++) {
            uint32_t a[2][4];
            #pragma unroll
            for (int mf = 0; mf < 2; mf++) {
                int r = m0 + mf * 16 + g;
                a[mf][0] = Ax[r * 20 + ks * 8 + t4];
                a[mf][1] = Ax[(r + 8) * 20 + ks * 8 + t4];
                a[mf][2] = Ax[r * 20 + ks * 8 + t4 + 4];
                a[mf][3] = Ax[(r + 8) * 20 + ks * 8 + t4 + 4];
            }
            #pragma unroll
            for (int nf = 0; nf < 4; nf++) {
                int rn = nw + nf * 8 + g;
                uint32_t b0 = Bx[rn * 20 + ks * 8 + t4];
                uint32_t b1 = Bx[rn * 20 + ks * 8 + t4 + 4];
                mma_f16(acc[0][nf], a[0], b0, b1);
                mma_f16(acc[1][nf], a[1], b0, b1);
            }
        }
        __syncthreads();
    }

    float* gxp = g_gx + ((size_t)(dir * T_SEQ + t) * NB) * 1024 + n0;
    #pragma unroll
    for (int mf = 0; mf < 2; mf++) {
        int bi = m0 + mf * 16 + g;
        #pragma unroll
        for (int nf = 0; nf < 4; nf++) {
            int nn = nw + nf * 8 + t4 * 2;
            float bv0 = bias_s[nn], bv1 = bias_s[nn + 1];
            float2 v0 = make_float2(acc[mf][nf][0] + bv0, acc[mf][nf][1] + bv1);
            float2 v1 = make_float2(acc[mf][nf][2] + bv0, acc[mf][nf][3] + bv1);
            *reinterpret_cast<float2*>(gxp + (size_t)bi * 1024 + nn)       = v0;
            *reinterpret_cast<float2*>(gxp + (size_t)(bi + 8) * 1024 + nn) = v1;
        }
    }
}

// =====================================================================
// Head
// =====================================================================
__global__ void __launch_bounds__(256) head_fc1(const float* __restrict__ fc1_w,
                                                const float* __restrict__ fc1_b)
{
    __shared__ __align__(16) float fs[512];
    int b = blockIdx.x, n = threadIdx.x;
    for (int i = n; i < 512; i += 256) fs[i] = g_feat[b * 512 + i];
    __syncthreads();
    const float4* wp = reinterpret_cast<const float4*>(fc1_w + (size_t)n * 512);
    const float4* fp = reinterpret_cast<const float4*>(fs);
    float acc = fc1_b[n];
    #pragma unroll 4
    for (int k = 0; k < 128; k++) {
        float4 w4 = __ldg(wp + k);
        float4 f4 = fp[k];
        acc += w4.x * f4.x + w4.y * f4.y + w4.z * f4.z + w4.w * f4.w;
    }
    g_y[b * 256 + n] = fmaxf(acc, 0.0f);
}

__global__ void head_bn(const float* __restrict__ gamma, const float* __restrict__ beta)
{
    int n = threadIdx.x;
    float s = 0.0f, s2 = 0.0f;
    for (int b = 0; b < 64; b++) {
        float v = g_y[b * 256 + n];
        s += v; s2 += v * v;
    }
    float mean = s * 0.015625f;
    float var  = s2 * 0.015625f - mean * mean;
    float inv  = rsqrtf(var + 1e-5f);
    float ga = gamma[n] * inv, be = beta[n];
    for (int b = 0; b < 64; b++)
        g_y[b * 256 + n] = (g_y[b * 256 + n] - mean) * ga + be;
}

__global__ void __launch_bounds__(256) head_out(const float* __restrict__ W,
                                                const float* __restrict__ bias,
                                                float* __restrict__ out)
{
    __shared__ __align__(16) float ys[256];
    int b = blockIdx.x;
    ys[threadIdx.x] = g_y[b * 256 + threadIdx.x];
    __syncthreads();
    int o = threadIdx.x;
    if (o < 196) {
        const float4* wp = reinterpret_cast<const float4*>(W + (size_t)o * 256);
        const float4* yp = reinterpret_cast<const float4*>(ys);
        float acc = bias[o];
        #pragma unroll 4
        for (int k = 0; k < 64; k++) {
            float4 w4 = __ldg(wp + k);
            float4 y4 = yp[k];
            acc += w4.x * y4.x + w4.y * y4.y + w4.z * y4.z + w4.w * y4.w;
        }
        out[(size_t)b * 196 + o] = acc;
    }
}

// =====================================================================
extern "C" void kernel_launch(void* const* d_in, const int* in_sizes, int n_in,
                              void* d_out, int out_size)
{
    const float* x       = (const float*)d_in[0];
    const int*   lengths = (const int*)  d_in[1];
    const float* Wih0    = (const float*)d_in[2];
    const float* Whh0    = (const float*)d_in[3];
    const float* bih0    = (const float*)d_in[4];
    const float* bhh0    = (const float*)d_in[5];
    const float* Wih1    = (const float*)d_in[6];
    const float* Whh1    = (const float*)d_in[7];
    const float* bih1    = (const float*)d_in[8];
    const float* bhh1    = (const float*)d_in[9];
    const float* fc1_w   = (const float*)d_in[10];
    const float* fc1_b   = (const float*)d_in[11];
    const float* gamma   = (const float*)d_in[12];
    const float* beta    = (const float*)d_in[13];
    const float* fcow    = (const float*)d_in[14];
    const float* fcob    = (const float*)d_in[15];
    float* out = (float*)d_out;

    conv_w1<<<1024, 256>>>(Wih1);
    lstm_rec<0><<<64, 256>>>(x, lengths, Wih0, Whh0, bih0, bhh0);
    gx_mma<<<dim3(8, 1024, 2), 256>>>(lengths, bih1, bhh1);
    lstm_rec<1><<<64, 256>>>(x, lengths, Wih1, Whh1, bih1, bhh1);
    head_fc1<<<64, 256>>>(fc1_w, fc1_b);
    head_bn<<<1, 256>>>(gamma, beta);
    head_out<<<64, 256>>>(fcow, fcob, out);
}